// round 3
// baseline (speedup 1.0000x reference)
#include <cuda_runtime.h>
#include <math.h>

#define BB   16
#define CIN  256
#define CC   512
#define LL   4096
#define DD   512
#define UMAX 512

// -------- scratch (device globals; allocation-free) --------
__device__ float g_q[(size_t)BB*LL*DD];
__device__ float g_k[(size_t)BB*LL*DD];
__device__ float g_v[(size_t)BB*LL*DD];
__device__ float g_ksamp[(size_t)BB*UMAX*DD];
__device__ float g_qks[(size_t)BB*LL*UMAX];
__device__ float g_M[(size_t)BB*LL];
__device__ int   g_mtop[(size_t)BB*UMAX];
__device__ float g_qr[(size_t)BB*UMAX*DD];
__device__ float g_scores[(size_t)BB*UMAX*LL];
__device__ float g_vmean[(size_t)BB*DD];
__device__ float g_upd[(size_t)BB*UMAX*DD];

// -------- generic tiled fp32 GEMM --------
// C[gm*ldc_m + gn*ldc_n] = alpha * sum_k A[m*lda_m + k*lda_k] * B[n*ldb_n + k*ldb_k] (+ bias[n])
// SPLITA: A channels split across two base pointers at k = Ksplit (concat fusion).
template<bool AKC, bool BKC, bool SPLITA>
__global__ void gemm_kernel(const float* __restrict__ A, const float* __restrict__ A2,
                            const float* __restrict__ Bm, float* __restrict__ C,
                            int M, int N, int K, int Ksplit,
                            long lda_m, long lda_k, long ldb_n, long ldb_k,
                            long ldc_m, long ldc_n,
                            long sA, long sB, long sC,
                            const float* __restrict__ bias, float alpha)
{
    __shared__ float As[16][65];
    __shared__ float Bs[16][65];
    int b = blockIdx.z;
    const float* Ab  = A  + (size_t)b * sA;
    const float* A2b = SPLITA ? (A2 + (size_t)b * sA) : nullptr;
    const float* Bb  = Bm + (size_t)b * sB;
    float*       Cb  = C  + (size_t)b * sC;
    int m0 = blockIdx.y * 64, n0 = blockIdx.x * 64;
    int tid = threadIdx.x;
    int tx = tid & 15, ty = tid >> 4;
    float acc[4][4] = {};

    for (int k0 = 0; k0 < K; k0 += 16) {
        #pragma unroll
        for (int i = 0; i < 4; i++) {
            int linear = tid + i * 256;
            int mm, kk;
            if (AKC) { kk = linear & 15; mm = linear >> 4; }
            else     { mm = linear & 63; kk = linear >> 6; }
            int gm = m0 + mm, gk = k0 + kk;
            float val = 0.f;
            if (gm < M) {
                if (SPLITA) {
                    val = (gk < Ksplit)
                        ? Ab [(size_t)gm * lda_m + (size_t)gk          * lda_k]
                        : A2b[(size_t)gm * lda_m + (size_t)(gk-Ksplit) * lda_k];
                } else {
                    val = Ab[(size_t)gm * lda_m + (size_t)gk * lda_k];
                }
            }
            As[kk][mm] = val;
        }
        #pragma unroll
        for (int i = 0; i < 4; i++) {
            int linear = tid + i * 256;
            int nn, kk;
            if (BKC) { kk = linear & 15; nn = linear >> 4; }
            else     { nn = linear & 63; kk = linear >> 6; }
            int gn = n0 + nn, gk = k0 + kk;
            float val = 0.f;
            if (gn < N) val = Bb[(size_t)gn * ldb_n + (size_t)gk * ldb_k];
            Bs[kk][nn] = val;
        }
        __syncthreads();
        #pragma unroll
        for (int kk = 0; kk < 16; kk++) {
            float ra[4], rb[4];
            #pragma unroll
            for (int i = 0; i < 4; i++) ra[i] = As[kk][ty + 16*i];
            #pragma unroll
            for (int j = 0; j < 4; j++) rb[j] = Bs[kk][tx + 16*j];
            #pragma unroll
            for (int i = 0; i < 4; i++)
                #pragma unroll
                for (int j = 0; j < 4; j++)
                    acc[i][j] += ra[i] * rb[j];
        }
        __syncthreads();
    }

    #pragma unroll
    for (int i = 0; i < 4; i++) {
        int gm = m0 + ty + 16*i;
        if (gm >= M) continue;
        #pragma unroll
        for (int j = 0; j < 4; j++) {
            int gn = n0 + tx + 16*j;
            if (gn >= N) continue;
            float v = acc[i][j] * alpha;
            if (bias) v += bias[gn];
            Cb[(size_t)gm * ldc_m + (size_t)gn * ldc_n] = v;
        }
    }
}

// -------- gather sampled K rows --------
__global__ void gather_ksample_kernel(const int* __restrict__ idx, int U) {
    size_t t = (size_t)blockIdx.x * blockDim.x + threadIdx.x;
    size_t total = (size_t)BB * U * DD;
    if (t >= total) return;
    int d = (int)(t % DD);
    size_t rest = t / DD;
    int s = (int)(rest % U);
    int b = (int)(rest / U);
    g_ksamp[((size_t)b * U + s) * DD + d] = g_k[((size_t)b * LL + idx[s]) * DD + d];
}

// -------- M[b,l] = max_s QKs - sum_s QKs / L --------
__global__ void reduce_M_kernel(int U) {
    int warp = (blockIdx.x * blockDim.x + threadIdx.x) >> 5;
    int lane = threadIdx.x & 31;
    if (warp >= BB * LL) return;
    const float* row = g_qks + (size_t)warp * U;
    float mx = -INFINITY, sm = 0.f;
    for (int s = lane; s < U; s += 32) { float x = row[s]; mx = fmaxf(mx, x); sm += x; }
    #pragma unroll
    for (int o = 16; o; o >>= 1) {
        mx = fmaxf(mx, __shfl_xor_sync(0xFFFFFFFFu, mx, o));
        sm += __shfl_xor_sync(0xFFFFFFFFu, sm, o);
    }
    if (lane == 0) g_M[warp] = mx - sm * (1.0f / (float)LL);
}

// -------- per-batch bitonic top-k (desc by value, ties -> lower index) --------
__global__ void topk_kernel(int u) {
    __shared__ float sv[LL];
    __shared__ int   si[LL];
    int b = blockIdx.x;
    for (int i = threadIdx.x; i < LL; i += blockDim.x) { sv[i] = g_M[(size_t)b*LL + i]; si[i] = i; }
    __syncthreads();
    for (int k = 2; k <= LL; k <<= 1) {
        for (int j = k >> 1; j > 0; j >>= 1) {
            for (int t = threadIdx.x; t < LL; t += blockDim.x) {
                int ixj = t ^ j;
                if (ixj > t) {
                    bool dirDesc = ((t & k) == 0);
                    float va = sv[t], vb = sv[ixj];
                    int   ia = si[t], ib = si[ixj];
                    bool aBeforeB = (va > vb) || (va == vb && ia < ib);
                    bool swp = dirDesc ? !aBeforeB : aBeforeB;
                    if (swp) { sv[t] = vb; sv[ixj] = va; si[t] = ib; si[ixj] = ia; }
                }
            }
            __syncthreads();
        }
    }
    for (int i = threadIdx.x; i < u; i += blockDim.x) g_mtop[(size_t)b*u + i] = si[i];
}

// -------- gather Q_reduce rows --------
__global__ void gather_qr_kernel(int u) {
    size_t t = (size_t)blockIdx.x * blockDim.x + threadIdx.x;
    size_t total = (size_t)BB * u * DD;
    if (t >= total) return;
    int d = (int)(t % DD);
    size_t rest = t / DD;
    int uu = (int)(rest % u);
    int b  = (int)(rest / u);
    int l = g_mtop[(size_t)b*u + uu];
    g_qr[((size_t)b*u + uu) * DD + d] = g_q[((size_t)b*LL + l) * DD + d];
}

// -------- row softmax over L (in place on scores) --------
__global__ void softmax_kernel() {
    __shared__ float row[LL];
    __shared__ float red[256];
    size_t r = blockIdx.x;
    float* ptr = g_scores + r * (size_t)LL;
    float mx = -INFINITY;
    for (int i = threadIdx.x; i < LL; i += 256) { float x = ptr[i]; row[i] = x; mx = fmaxf(mx, x); }
    red[threadIdx.x] = mx; __syncthreads();
    for (int s = 128; s; s >>= 1) { if (threadIdx.x < s) red[threadIdx.x] = fmaxf(red[threadIdx.x], red[threadIdx.x+s]); __syncthreads(); }
    mx = red[0]; __syncthreads();
    float sm = 0.f;
    for (int i = threadIdx.x; i < LL; i += 256) { float e = __expf(row[i] - mx); row[i] = e; sm += e; }
    red[threadIdx.x] = sm; __syncthreads();
    for (int s = 128; s; s >>= 1) { if (threadIdx.x < s) red[threadIdx.x] += red[threadIdx.x+s]; __syncthreads(); }
    float inv = 1.f / red[0];
    for (int i = threadIdx.x; i < LL; i += 256) ptr[i] = row[i] * inv;
}

// -------- v mean over L --------
__global__ void vmean_zero_kernel() {
    int i = blockIdx.x * blockDim.x + threadIdx.x;
    if (i < BB * DD) g_vmean[i] = 0.f;
}
__global__ void vmean_kernel() {
    int b = blockIdx.x, ch = blockIdx.y;
    int d = threadIdx.x;
    float s = 0.f;
    int l0 = ch * 128;
    for (int l = l0; l < l0 + 128; l++) s += g_v[((size_t)b*LL + l) * DD + d];
    atomicAdd(&g_vmean[b*DD + d], s * (1.0f / (float)LL));
}

// -------- output: broadcast mean then scatter updated rows --------
// out flat per batch == context[b] in (L, D) row-major (transpose+reshape is flat).
__global__ void broadcast_out_kernel(float* __restrict__ out) {
    size_t t = (size_t)blockIdx.x * blockDim.x + threadIdx.x;
    if (t >= (size_t)BB*LL*DD) return;
    int d = (int)(t % DD);
    int b = (int)(t / ((size_t)LL*DD));
    out[t] = g_vmean[b*DD + d];
}
__global__ void scatter_out_kernel(float* __restrict__ out, int u) {
    size_t t = (size_t)blockIdx.x * blockDim.x + threadIdx.x;
    size_t total = (size_t)BB * u * DD;
    if (t >= total) return;
    int d = (int)(t % DD);
    size_t rest = t / DD;
    int uu = (int)(rest % u);
    int b  = (int)(rest / u);
    int l = g_mtop[(size_t)b*u + uu];
    out[((size_t)b*LL + l) * DD + d] = g_upd[((size_t)b*u + uu) * DD + d];
}

extern "C" void kernel_launch(void* const* d_in, const int* in_sizes, int n_in,
                              void* d_out, int out_size)
{
    const float* in1 = (const float*)d_in[0];
    const float* in2 = (const float*)d_in[1];
    const float* Wq  = (const float*)d_in[2];
    const float* bq  = (const float*)d_in[3];
    const float* Wk  = (const float*)d_in[4];
    const float* bk  = (const float*)d_in[5];
    const float* Wv  = (const float*)d_in[6];
    const float* bv  = (const float*)d_in[7];
    const int*   idx = (const int*)d_in[8];
    int U = in_sizes[8];
    int u = (U < LL) ? U : LL;
    float* out = (float*)d_out;

    float *q, *k, *v, *ksamp, *qks, *qr, *scores, *upd;
    cudaGetSymbolAddress((void**)&q,      g_q);
    cudaGetSymbolAddress((void**)&k,      g_k);
    cudaGetSymbolAddress((void**)&v,      g_v);
    cudaGetSymbolAddress((void**)&ksamp,  g_ksamp);
    cudaGetSymbolAddress((void**)&qks,    g_qks);
    cudaGetSymbolAddress((void**)&qr,     g_qr);
    cudaGetSymbolAddress((void**)&scores, g_scores);
    cudaGetSymbolAddress((void**)&upd,    g_upd);

    dim3 blk(256);
    const float scale = rsqrtf(512.0f);  // 1/sqrt(IN_CHANNELS)

    // 1) projections: y[b,o,s] = sum_c x[b,c,s]*W[o,c] + b[o], stored flat as
    //    y[o*L + s] which IS the (L,D)-row-major view of q/k/v after the
    //    reference's flat reshape (B,D,W,H)->(B,1,L,D).
    //    GEMM: gm = spatial s (M=LL), gn = channel o (N=DD); output transposed:
    //    ldc_m = 1, ldc_n = LL.
    {
        dim3 grid(DD/64, LL/64, BB);
        gemm_kernel<false,true,true><<<grid, blk>>>(in1, in2, Wq, q, LL, DD, CC, CIN,
            1L, (long)LL, (long)CC, 1L, 1L, (long)LL, (long)CIN*LL, 0L, (long)LL*DD, bq, 1.0f);
        gemm_kernel<false,true,true><<<grid, blk>>>(in1, in2, Wk, k, LL, DD, CC, CIN,
            1L, (long)LL, (long)CC, 1L, 1L, (long)LL, (long)CIN*LL, 0L, (long)LL*DD, bk, 1.0f);
        gemm_kernel<false,true,true><<<grid, blk>>>(in1, in2, Wv, v, LL, DD, CC, CIN,
            1L, (long)LL, (long)CC, 1L, 1L, (long)LL, (long)CIN*LL, 0L, (long)LL*DD, bv, 1.0f);
    }

    // 2) gather sampled K rows
    {
        size_t total = (size_t)BB * U * DD;
        gather_ksample_kernel<<<(unsigned)((total + 255) / 256), blk>>>(idx, U);
    }

    // 3) QKs[l,s] = q[l,:] . ksamp[s,:]
    {
        dim3 grid((U + 63)/64, LL/64, BB);
        gemm_kernel<true,true,false><<<grid, blk>>>(q, nullptr, ksamp, qks, LL, U, DD, 0,
            (long)DD, 1L, (long)DD, 1L, (long)U, 1L, (long)LL*DD, (long)U*DD, (long)LL*U, nullptr, 1.0f);
    }

    // 4) M and top-k
    reduce_M_kernel<<<(BB*LL*32 + 255)/256, blk>>>(U);
    topk_kernel<<<BB, 1024>>>(u);

    // 5) gather Q_reduce
    {
        size_t total = (size_t)BB * u * DD;
        gather_qr_kernel<<<(unsigned)((total + 255) / 256), blk>>>(u);
    }

    // 6) scores[u,l] = (Qr[u,:] . k[l,:]) * scale
    {
        dim3 grid(LL/64, (u + 63)/64, BB);
        gemm_kernel<true,true,false><<<grid, blk>>>(qr, nullptr, k, scores, u, LL, DD, 0,
            (long)DD, 1L, (long)DD, 1L, (long)LL, 1L, (long)u*DD, (long)LL*DD, (long)u*LL, nullptr, scale);
    }

    // 7) softmax over L (in place)
    softmax_kernel<<<BB*u, blk>>>();

    // 8) upd[u,d] = sum_l attn[u,l]*v[l,d]
    {
        dim3 grid(DD/64, (u + 63)/64, BB);
        gemm_kernel<true,false,false><<<grid, blk>>>(scores, nullptr, v, upd, u, DD, LL, 0,
            (long)LL, 1L, 1L, (long)DD, (long)DD, 1L, (long)u*LL, (long)LL*DD, (long)u*DD, nullptr, 1.0f);
    }

    // 9) v mean, broadcast, scatter
    vmean_zero_kernel<<<(BB*DD + 255)/256, blk>>>();
    {
        dim3 grid(BB, 32);
        vmean_kernel<<<grid, DD>>>();
    }
    {
        size_t total = (size_t)BB * LL * DD;
        broadcast_out_kernel<<<(unsigned)((total + 255)/256), blk>>>(out);
        size_t st = (size_t)BB * u * DD;
        scatter_out_kernel<<<(unsigned)((st + 255)/256), blk>>>(out, u);
    }
}

// round 7
// speedup vs baseline: 1.3795x; 1.3795x over previous
#include <cuda_runtime.h>
#include <math.h>
#include <stdint.h>

#define BB   16
#define CIN  256
#define CC   512
#define LL   4096
#define DD   512
#define UMAX 512

// -------- scratch (device globals; allocation-free) --------
__device__ float g_q[(size_t)BB*LL*DD];
__device__ float g_k[(size_t)BB*LL*DD];
__device__ float g_v[(size_t)BB*LL*DD];
__device__ float g_ksamp[(size_t)BB*UMAX*DD];
__device__ float g_qks[(size_t)BB*LL*UMAX];
__device__ float g_M[(size_t)BB*LL];
__device__ int   g_mtop[(size_t)BB*UMAX];
__device__ float g_qr[(size_t)BB*UMAX*DD];
__device__ float g_scores[(size_t)BB*UMAX*LL];
__device__ float g_vmean[(size_t)BB*DD];
__device__ float g_upd[(size_t)BB*UMAX*DD];

// -------- tf32 helpers --------
__device__ __forceinline__ uint32_t f2tf32(float a) {
    uint32_t r;
    asm("cvt.rna.tf32.f32 %0, %1;" : "=r"(r) : "f"(a));
    return r;
}
__device__ __forceinline__ void mma_tf32(float c[4],
                                         uint32_t a0, uint32_t a1, uint32_t a2, uint32_t a3,
                                         uint32_t b0, uint32_t b1) {
    asm("mma.sync.aligned.m16n8k8.row.col.f32.tf32.tf32.f32 "
        "{%0,%1,%2,%3},{%4,%5,%6,%7},{%8,%9},{%0,%1,%2,%3};"
        : "+f"(c[0]), "+f"(c[1]), "+f"(c[2]), "+f"(c[3])
        : "r"(a0), "r"(a1), "r"(a2), "r"(a3), "r"(b0), "r"(b1));
}

// -------- generic tiled GEMM on tensor cores (tf32 / 3xtf32) --------
// C[gm*ldc_m + gn*ldc_n] = alpha * sum_k A[m*lda_m + k*lda_k] * B[n*ldb_n + k*ldb_k] (+ bias[n])
// SPLITA: A channels split across two base pointers at k = Ksplit (concat fusion).
// XA = 3: error-compensated 3xTF32 (fp32-level accuracy). XA = 1: plain tf32.
template<bool AKC, bool BKC, bool SPLITA, int XA>
__global__ void gemm_tc_kernel(const float* __restrict__ A, const float* __restrict__ A2,
                               const float* __restrict__ Bm, float* __restrict__ C,
                               int M, int N, int K, int Ksplit,
                               long lda_m, long lda_k, long ldb_n, long ldb_k,
                               long ldc_m, long ldc_n,
                               long sA, long sB, long sC,
                               const float* __restrict__ bias, float alpha)
{
    __shared__ float As[16][72];   // stride 72: conflict-free quad fragment loads
    __shared__ float Bs[16][72];
    int b = blockIdx.z;
    const float* Ab  = A  + (size_t)b * sA;
    const float* A2b = SPLITA ? (A2 + (size_t)b * sA) : nullptr;
    const float* Bb  = Bm + (size_t)b * sB;
    float*       Cb  = C  + (size_t)b * sC;
    int m0 = blockIdx.y * 64, n0 = blockIdx.x * 64;
    int tid  = threadIdx.x;
    int wid  = tid >> 5, lane = tid & 31;
    int wm = (wid & 1) * 32;        // warp m-offset within 64
    int wn = (wid >> 1) * 16;       // warp n-offset within 64
    int lr = lane >> 2, lc = lane & 3;

    float acc[2][2][4];
    #pragma unroll
    for (int i = 0; i < 2; i++)
        #pragma unroll
        for (int j = 0; j < 2; j++)
            #pragma unroll
            for (int t = 0; t < 4; t++) acc[i][j][t] = 0.f;

    for (int k0 = 0; k0 < K; k0 += 16) {
        // ---- load A tile into As[k][m] ----
        #pragma unroll
        for (int i = 0; i < 4; i++) {
            int linear = tid + i * 256;
            int mm, kk;
            if (AKC) { kk = linear & 15; mm = linear >> 4; }
            else     { mm = linear & 63; kk = linear >> 6; }
            int gm = m0 + mm, gk = k0 + kk;
            float val = 0.f;
            if (gm < M) {
                if (SPLITA) {
                    val = (gk < Ksplit)
                        ? Ab [(size_t)gm * lda_m + (size_t)gk          * lda_k]
                        : A2b[(size_t)gm * lda_m + (size_t)(gk-Ksplit) * lda_k];
                } else {
                    val = Ab[(size_t)gm * lda_m + (size_t)gk * lda_k];
                }
            }
            As[kk][mm] = val;
        }
        // ---- load B tile into Bs[k][n] ----
        #pragma unroll
        for (int i = 0; i < 4; i++) {
            int linear = tid + i * 256;
            int nn, kk;
            if (BKC) { kk = linear & 15; nn = linear >> 4; }
            else     { nn = linear & 63; kk = linear >> 6; }
            int gn = n0 + nn, gk = k0 + kk;
            float val = 0.f;
            if (gn < N) val = Bb[(size_t)gn * ldb_n + (size_t)gk * ldb_k];
            Bs[kk][nn] = val;
        }
        __syncthreads();

        // ---- tensor-core compute: two k=8 sub-slabs ----
        #pragma unroll
        for (int kt = 0; kt < 2; kt++) {
            int kb = kt * 8;
            uint32_t ah[2][4], al[2][4], bh[2][2], bl[2][2];
            #pragma unroll
            for (int mt = 0; mt < 2; mt++) {
                float v0 = As[kb + lc    ][wm + mt*16 + lr    ];
                float v1 = As[kb + lc    ][wm + mt*16 + lr + 8];
                float v2 = As[kb + lc + 4][wm + mt*16 + lr    ];
                float v3 = As[kb + lc + 4][wm + mt*16 + lr + 8];
                ah[mt][0] = f2tf32(v0); ah[mt][1] = f2tf32(v1);
                ah[mt][2] = f2tf32(v2); ah[mt][3] = f2tf32(v3);
                if (XA == 3) {
                    al[mt][0] = f2tf32(v0 - __uint_as_float(ah[mt][0]));
                    al[mt][1] = f2tf32(v1 - __uint_as_float(ah[mt][1]));
                    al[mt][2] = f2tf32(v2 - __uint_as_float(ah[mt][2]));
                    al[mt][3] = f2tf32(v3 - __uint_as_float(ah[mt][3]));
                }
            }
            #pragma unroll
            for (int nt = 0; nt < 2; nt++) {
                float w0 = Bs[kb + lc    ][wn + nt*8 + lr];
                float w1 = Bs[kb + lc + 4][wn + nt*8 + lr];
                bh[nt][0] = f2tf32(w0); bh[nt][1] = f2tf32(w1);
                if (XA == 3) {
                    bl[nt][0] = f2tf32(w0 - __uint_as_float(bh[nt][0]));
                    bl[nt][1] = f2tf32(w1 - __uint_as_float(bh[nt][1]));
                }
            }
            #pragma unroll
            for (int mt = 0; mt < 2; mt++)
                #pragma unroll
                for (int nt = 0; nt < 2; nt++) {
                    if (XA == 3) {
                        mma_tf32(acc[mt][nt], ah[mt][0], ah[mt][1], ah[mt][2], ah[mt][3],
                                 bl[nt][0], bl[nt][1]);
                        mma_tf32(acc[mt][nt], al[mt][0], al[mt][1], al[mt][2], al[mt][3],
                                 bh[nt][0], bh[nt][1]);
                    }
                    mma_tf32(acc[mt][nt], ah[mt][0], ah[mt][1], ah[mt][2], ah[mt][3],
                             bh[nt][0], bh[nt][1]);
                }
        }
        __syncthreads();
    }

    // ---- epilogue: mma C-fragment layout ----
    #pragma unroll
    for (int mt = 0; mt < 2; mt++) {
        #pragma unroll
        for (int nt = 0; nt < 2; nt++) {
            int gr0 = m0 + wm + mt*16 + lr;
            int gc0 = n0 + wn + nt*8 + 2*lc;
            #pragma unroll
            for (int t = 0; t < 4; t++) {
                int gm = gr0 + ((t >= 2) ? 8 : 0);
                int gn = gc0 + (t & 1);
                if (gm >= M || gn >= N) continue;
                float v = acc[mt][nt][t] * alpha;
                if (bias) v += bias[gn];
                Cb[(size_t)gm * ldc_m + (size_t)gn * ldc_n] = v;
            }
        }
    }
}

// -------- gather sampled K rows --------
__global__ void gather_ksample_kernel(const int* __restrict__ idx, int U) {
    size_t t = (size_t)blockIdx.x * blockDim.x + threadIdx.x;
    size_t total = (size_t)BB * U * DD;
    if (t >= total) return;
    int d = (int)(t % DD);
    size_t rest = t / DD;
    int s = (int)(rest % U);
    int b = (int)(rest / U);
    g_ksamp[((size_t)b * U + s) * DD + d] = g_k[((size_t)b * LL + idx[s]) * DD + d];
}

// -------- M[b,l] = max_s QKs - sum_s QKs / L --------
__global__ void reduce_M_kernel(int U) {
    int warp = (blockIdx.x * blockDim.x + threadIdx.x) >> 5;
    int lane = threadIdx.x & 31;
    if (warp >= BB * LL) return;
    const float* row = g_qks + (size_t)warp * U;
    float mx = -INFINITY, sm = 0.f;
    for (int s = lane; s < U; s += 32) { float x = row[s]; mx = fmaxf(mx, x); sm += x; }
    #pragma unroll
    for (int o = 16; o; o >>= 1) {
        mx = fmaxf(mx, __shfl_xor_sync(0xFFFFFFFFu, mx, o));
        sm += __shfl_xor_sync(0xFFFFFFFFu, sm, o);
    }
    if (lane == 0) g_M[warp] = mx - sm * (1.0f / (float)LL);
}

// -------- per-batch bitonic top-k (desc by value, ties -> lower index) --------
__global__ void topk_kernel(int u) {
    __shared__ float sv[LL];
    __shared__ int   si[LL];
    int b = blockIdx.x;
    for (int i = threadIdx.x; i < LL; i += blockDim.x) { sv[i] = g_M[(size_t)b*LL + i]; si[i] = i; }
    __syncthreads();
    for (int k = 2; k <= LL; k <<= 1) {
        for (int j = k >> 1; j > 0; j >>= 1) {
            for (int t = threadIdx.x; t < LL; t += blockDim.x) {
                int ixj = t ^ j;
                if (ixj > t) {
                    bool dirDesc = ((t & k) == 0);
                    float va = sv[t], vb = sv[ixj];
                    int   ia = si[t], ib = si[ixj];
                    bool aBeforeB = (va > vb) || (va == vb && ia < ib);
                    bool swp = dirDesc ? !aBeforeB : aBeforeB;
                    if (swp) { sv[t] = vb; sv[ixj] = va; si[t] = ib; si[ixj] = ia; }
                }
            }
            __syncthreads();
        }
    }
    for (int i = threadIdx.x; i < u; i += blockDim.x) g_mtop[(size_t)b*u + i] = si[i];
}

// -------- gather Q_reduce rows --------
__global__ void gather_qr_kernel(int u) {
    size_t t = (size_t)blockIdx.x * blockDim.x + threadIdx.x;
    size_t total = (size_t)BB * u * DD;
    if (t >= total) return;
    int d = (int)(t % DD);
    size_t rest = t / DD;
    int uu = (int)(rest % u);
    int b  = (int)(rest / u);
    int l = g_mtop[(size_t)b*u + uu];
    g_qr[((size_t)b*u + uu) * DD + d] = g_q[((size_t)b*LL + l) * DD + d];
}

// -------- row softmax over L (in place on scores) --------
__global__ void softmax_kernel() {
    __shared__ float row[LL];
    __shared__ float red[256];
    size_t r = blockIdx.x;
    float* ptr = g_scores + r * (size_t)LL;
    float mx = -INFINITY;
    for (int i = threadIdx.x; i < LL; i += 256) { float x = ptr[i]; row[i] = x; mx = fmaxf(mx, x); }
    red[threadIdx.x] = mx; __syncthreads();
    for (int s = 128; s; s >>= 1) { if (threadIdx.x < s) red[threadIdx.x] = fmaxf(red[threadIdx.x], red[threadIdx.x+s]); __syncthreads(); }
    mx = red[0]; __syncthreads();
    float sm = 0.f;
    for (int i = threadIdx.x; i < LL; i += 256) { float e = __expf(row[i] - mx); row[i] = e; sm += e; }
    red[threadIdx.x] = sm; __syncthreads();
    for (int s = 128; s; s >>= 1) { if (threadIdx.x < s) red[threadIdx.x] += red[threadIdx.x+s]; __syncthreads(); }
    float inv = 1.f / red[0];
    for (int i = threadIdx.x; i < LL; i += 256) ptr[i] = row[i] * inv;
}

// -------- v mean over L --------
__global__ void vmean_zero_kernel() {
    int i = blockIdx.x * blockDim.x + threadIdx.x;
    if (i < BB * DD) g_vmean[i] = 0.f;
}
__global__ void vmean_kernel() {
    int b = blockIdx.x, ch = blockIdx.y;
    int d = threadIdx.x;
    float s = 0.f;
    int l0 = ch * 128;
    for (int l = l0; l < l0 + 128; l++) s += g_v[((size_t)b*LL + l) * DD + d];
    atomicAdd(&g_vmean[b*DD + d], s * (1.0f / (float)LL));
}

// -------- output: broadcast mean then scatter updated rows --------
__global__ void broadcast_out_kernel(float* __restrict__ out) {
    size_t t = (size_t)blockIdx.x * blockDim.x + threadIdx.x;
    if (t >= (size_t)BB*LL*DD) return;
    int d = (int)(t % DD);
    int b = (int)(t / ((size_t)LL*DD));
    out[t] = g_vmean[b*DD + d];
}
__global__ void scatter_out_kernel(float* __restrict__ out, int u) {
    size_t t = (size_t)blockIdx.x * blockDim.x + threadIdx.x;
    size_t total = (size_t)BB * u * DD;
    if (t >= total) return;
    int d = (int)(t % DD);
    size_t rest = t / DD;
    int uu = (int)(rest % u);
    int b  = (int)(rest / u);
    int l = g_mtop[(size_t)b*u + uu];
    out[((size_t)b*LL + l) * DD + d] = g_upd[((size_t)b*u + uu) * DD + d];
}

extern "C" void kernel_launch(void* const* d_in, const int* in_sizes, int n_in,
                              void* d_out, int out_size)
{
    const float* in1 = (const float*)d_in[0];
    const float* in2 = (const float*)d_in[1];
    const float* Wq  = (const float*)d_in[2];
    const float* bq  = (const float*)d_in[3];
    const float* Wk  = (const float*)d_in[4];
    const float* bk  = (const float*)d_in[5];
    const float* Wv  = (const float*)d_in[6];
    const float* bv  = (const float*)d_in[7];
    const int*   idx = (const int*)d_in[8];
    int U = in_sizes[8];
    int u = (U < LL) ? U : LL;
    float* out = (float*)d_out;

    float *q, *k, *v, *ksamp, *qks, *qr, *scores, *upd;
    cudaGetSymbolAddress((void**)&q,      g_q);
    cudaGetSymbolAddress((void**)&k,      g_k);
    cudaGetSymbolAddress((void**)&v,      g_v);
    cudaGetSymbolAddress((void**)&ksamp,  g_ksamp);
    cudaGetSymbolAddress((void**)&qks,    g_qks);
    cudaGetSymbolAddress((void**)&qr,     g_qr);
    cudaGetSymbolAddress((void**)&scores, g_scores);
    cudaGetSymbolAddress((void**)&upd,    g_upd);

    dim3 blk(256);
    const float scale = rsqrtf(512.0f);  // 1/sqrt(IN_CHANNELS)

    // 1) projections (3xTF32, fp32-level accuracy): y[o*L+s] = sum_c x[b,c,s]W[o,c]+b[o]
    //    (flat y IS the (L,D)-row-major q/k/v view after the reference reshape)
    {
        dim3 grid(DD/64, LL/64, BB);
        gemm_tc_kernel<false,true,true,3><<<grid, blk>>>(in1, in2, Wq, q, LL, DD, CC, CIN,
            1L, (long)LL, (long)CC, 1L, 1L, (long)LL, (long)CIN*LL, 0L, (long)LL*DD, bq, 1.0f);
        gemm_tc_kernel<false,true,true,3><<<grid, blk>>>(in1, in2, Wk, k, LL, DD, CC, CIN,
            1L, (long)LL, (long)CC, 1L, 1L, (long)LL, (long)CIN*LL, 0L, (long)LL*DD, bk, 1.0f);
        gemm_tc_kernel<false,true,true,3><<<grid, blk>>>(in1, in2, Wv, v, LL, DD, CC, CIN,
            1L, (long)LL, (long)CC, 1L, 1L, (long)LL, (long)CIN*LL, 0L, (long)LL*DD, bv, 1.0f);
    }

    // 2) gather sampled K rows
    {
        size_t total = (size_t)BB * U * DD;
        gather_ksample_kernel<<<(unsigned)((total + 255) / 256), blk>>>(idx, U);
    }

    // 3) QKs[l,s] = q[l,:] . ksamp[s,:]   (3xTF32 — feeds discrete top-k)
    {
        dim3 grid((U + 63)/64, LL/64, BB);
        gemm_tc_kernel<true,true,false,3><<<grid, blk>>>(q, nullptr, ksamp, qks, LL, U, DD, 0,
            (long)DD, 1L, (long)DD, 1L, (long)U, 1L, (long)LL*DD, (long)U*DD, (long)LL*U, nullptr, 1.0f);
    }

    // 4) M and top-k
    reduce_M_kernel<<<(BB*LL*32 + 255)/256, blk>>>(U);
    topk_kernel<<<BB, 1024>>>(u);

    // 5) gather Q_reduce
    {
        size_t total = (size_t)BB * u * DD;
        gather_qr_kernel<<<(unsigned)((total + 255) / 256), blk>>>(u);
    }

    // 6) scores[u,l] = (Qr[u,:] . k[l,:]) * scale   (1xTF32, smooth path)
    {
        dim3 grid(LL/64, (u + 63)/64, BB);
        gemm_tc_kernel<true,true,false,1><<<grid, blk>>>(qr, nullptr, k, scores, u, LL, DD, 0,
            (long)DD, 1L, (long)DD, 1L, (long)LL, 1L, (long)u*DD, (long)LL*DD, (long)u*LL, nullptr, scale);
    }

    // 7) softmax over L (in place)
    softmax_kernel<<<BB*u, blk>>>();

    // 8) upd[u,d] = sum_l attn[u,l]*v[l,d]   (1xTF32, smooth path)
    {
        dim3 grid(DD/64, (u + 63)/64, BB);
        gemm_tc_kernel<true,false,false,1><<<grid, blk>>>(scores, nullptr, v, upd, u, DD, LL, 0,
            (long)LL, 1L, 1L, (long)DD, (long)DD, 1L, (long)u*LL, (long)LL*DD, (long)u*DD, nullptr, 1.0f);
    }

    // 9) v mean, broadcast, scatter
    vmean_zero_kernel<<<(BB*DD + 255)/256, blk>>>();
    {
        dim3 grid(BB, 32);
        vmean_kernel<<<grid, DD>>>();
    }
    {
        size_t total = (size_t)BB * LL * DD;
        broadcast_out_kernel<<<(unsigned)((total + 255)/256), blk>>>(out);
        size_t st = (size_t)BB * u * DD;
        scatter_out_kernel<<<(unsigned)((st + 255)/256), blk>>>(out, u);
    }
}

// round 9
// speedup vs baseline: 2.0111x; 1.4579x over previous
#include <cuda_runtime.h>
#include <math.h>
#include <stdint.h>

#define BB   16
#define CIN  256
#define CC   512
#define LL   4096
#define DD   512
#define UMAX 512

// -------- scratch (device globals; allocation-free) --------
__device__ float    g_q[(size_t)BB*LL*DD];
__device__ float    g_k[(size_t)BB*LL*DD];
__device__ float    g_v[(size_t)BB*LL*DD];
__device__ float    g_ksamp[(size_t)BB*UMAX*DD];
__device__ unsigned g_Mmax[(size_t)BB*LL];
__device__ float    g_Msum[(size_t)BB*LL];
__device__ int      g_mtop[(size_t)BB*UMAX];
__device__ float    g_qr[(size_t)BB*UMAX*DD];
__device__ float    g_scores[(size_t)BB*UMAX*LL];
__device__ float    g_vmean[(size_t)BB*DD];
__device__ float    g_upd[(size_t)BB*UMAX*DD];

// -------- tf32 helpers --------
__device__ __forceinline__ float tf32r(float a) {
    uint32_t r;
    asm("cvt.rna.tf32.f32 %0, %1;" : "=r"(r) : "f"(a));
    return __uint_as_float(r);
}
__device__ __forceinline__ void mma_tf32(float c[4],
                                         uint32_t a0, uint32_t a1, uint32_t a2, uint32_t a3,
                                         uint32_t b0, uint32_t b1) {
    asm("mma.sync.aligned.m16n8k8.row.col.f32.tf32.tf32.f32 "
        "{%0,%1,%2,%3},{%4,%5,%6,%7},{%8,%9},{%0,%1,%2,%3};"
        : "+f"(c[0]), "+f"(c[1]), "+f"(c[2]), "+f"(c[3])
        : "r"(a0), "r"(a1), "r"(a2), "r"(a3), "r"(b0), "r"(b1));
}

// order-preserving float<->uint key for atomicMax
__device__ __forceinline__ unsigned fkey(float f) {
    unsigned u = __float_as_uint(f);
    return (u & 0x80000000u) ? ~u : (u | 0x80000000u);
}
__device__ __forceinline__ float fdecode(unsigned k) {
    return (k & 0x80000000u) ? __uint_as_float(k ^ 0x80000000u) : __uint_as_float(~k);
}

// -------- tiled tensor-core GEMM, 128x64 block, 8 warps, 32x32 warp tile --------
// C[gm*ldc_m + gn*ldc_n] = alpha * sum_k A[..] * B[..] (+ bias[n])
// XA=3: error-compensated 3xTF32 (hi/lo pre-split in smem). XA=1: plain tf32.
// FUSEM: no C write; instead per-row atomic max & sum of the (unscaled) products
// into Mmax/Msum (+ b*LL) -- used by the QKs->M fusion.
template<bool AKC, bool BKC, bool SPLITA, int XA, bool FUSEM>
__global__ void __launch_bounds__(256)
gemm_tc_kernel(const float* __restrict__ A, const float* __restrict__ A2,
               const float* __restrict__ Bm, float* __restrict__ C,
               int M, int N, int K, int Ksplit,
               long lda_m, long lda_k, long ldb_n, long ldb_k,
               long ldc_m, long ldc_n,
               long sA, long sB, long sC,
               const float* __restrict__ bias, float alpha,
               unsigned* __restrict__ Mmax, float* __restrict__ Msum)
{
    __shared__ float As_hi[16][136];
    __shared__ float As_lo[16][136];
    __shared__ float Bs_hi[16][72];
    __shared__ float Bs_lo[16][72];

    int b = blockIdx.z;
    const float* Ab  = A  + (size_t)b * sA;
    const float* A2b = SPLITA ? (A2 + (size_t)b * sA) : nullptr;
    const float* Bb  = Bm + (size_t)b * sB;
    float*       Cb  = C  + (size_t)b * sC;
    int m0 = blockIdx.y * 128, n0 = blockIdx.x * 64;
    int tid  = threadIdx.x;
    int wid  = tid >> 5, lane = tid & 31;
    int wm = (wid & 3) * 32;      // warp m-offset in 128
    int wn = (wid >> 2) * 32;     // warp n-offset in 64
    int lr = lane >> 2, lc = lane & 3;

    float acc[2][4][4];
    #pragma unroll
    for (int i = 0; i < 2; i++)
        #pragma unroll
        for (int j = 0; j < 4; j++)
            #pragma unroll
            for (int t = 0; t < 4; t++) acc[i][j][t] = 0.f;

    float aPre[8], bPre[4];

    auto gload = [&](int k0) {
        #pragma unroll
        for (int i = 0; i < 8; i++) {
            int linear = tid + i * 256;
            int mm, kk;
            if (AKC) { kk = linear & 15;  mm = linear >> 4; }
            else     { mm = linear & 127; kk = linear >> 7; }
            int gm = m0 + mm, gk = k0 + kk;
            float val = 0.f;
            if (gm < M) {
                if (SPLITA) {
                    val = (gk < Ksplit)
                        ? Ab [(size_t)gm * lda_m + (size_t)gk          * lda_k]
                        : A2b[(size_t)gm * lda_m + (size_t)(gk-Ksplit) * lda_k];
                } else {
                    val = Ab[(size_t)gm * lda_m + (size_t)gk * lda_k];
                }
            }
            aPre[i] = val;
        }
        #pragma unroll
        for (int i = 0; i < 4; i++) {
            int linear = tid + i * 256;
            int nn, kk;
            if (BKC) { kk = linear & 15; nn = linear >> 4; }
            else     { nn = linear & 63; kk = linear >> 6; }
            int gn = n0 + nn, gk = k0 + kk;
            float val = 0.f;
            if (gn < N) val = Bb[(size_t)gn * ldb_n + (size_t)gk * ldb_k];
            bPre[i] = val;
        }
    };

    auto stile = [&]() {
        #pragma unroll
        for (int i = 0; i < 8; i++) {
            int linear = tid + i * 256;
            int mm, kk;
            if (AKC) { kk = linear & 15;  mm = linear >> 4; }
            else     { mm = linear & 127; kk = linear >> 7; }
            float v = aPre[i];
            float h = tf32r(v);
            As_hi[kk][mm] = h;
            if (XA == 3) As_lo[kk][mm] = tf32r(v - h);
        }
        #pragma unroll
        for (int i = 0; i < 4; i++) {
            int linear = tid + i * 256;
            int nn, kk;
            if (BKC) { kk = linear & 15; nn = linear >> 4; }
            else     { nn = linear & 63; kk = linear >> 6; }
            float v = bPre[i];
            float h = tf32r(v);
            Bs_hi[kk][nn] = h;
            if (XA == 3) Bs_lo[kk][nn] = tf32r(v - h);
        }
    };

    gload(0);
    for (int k0 = 0; k0 < K; k0 += 16) {
        stile();
        __syncthreads();
        if (k0 + 16 < K) gload(k0 + 16);

        #pragma unroll
        for (int kt = 0; kt < 2; kt++) {
            int kb = kt * 8;
            uint32_t ah[2][4], al[2][4];
            #pragma unroll
            for (int mt = 0; mt < 2; mt++) {
                int mb = wm + mt * 16;
                ah[mt][0] = __float_as_uint(As_hi[kb+lc  ][mb+lr  ]);
                ah[mt][1] = __float_as_uint(As_hi[kb+lc  ][mb+lr+8]);
                ah[mt][2] = __float_as_uint(As_hi[kb+lc+4][mb+lr  ]);
                ah[mt][3] = __float_as_uint(As_hi[kb+lc+4][mb+lr+8]);
                if (XA == 3) {
                    al[mt][0] = __float_as_uint(As_lo[kb+lc  ][mb+lr  ]);
                    al[mt][1] = __float_as_uint(As_lo[kb+lc  ][mb+lr+8]);
                    al[mt][2] = __float_as_uint(As_lo[kb+lc+4][mb+lr  ]);
                    al[mt][3] = __float_as_uint(As_lo[kb+lc+4][mb+lr+8]);
                }
            }
            #pragma unroll
            for (int nt = 0; nt < 4; nt++) {
                int nb = wn + nt * 8;
                uint32_t b0 = __float_as_uint(Bs_hi[kb+lc  ][nb+lr]);
                uint32_t b1 = __float_as_uint(Bs_hi[kb+lc+4][nb+lr]);
                uint32_t l0 = 0, l1 = 0;
                if (XA == 3) {
                    l0 = __float_as_uint(Bs_lo[kb+lc  ][nb+lr]);
                    l1 = __float_as_uint(Bs_lo[kb+lc+4][nb+lr]);
                }
                #pragma unroll
                for (int mt = 0; mt < 2; mt++) {
                    if (XA == 3) {
                        mma_tf32(acc[mt][nt], ah[mt][0], ah[mt][1], ah[mt][2], ah[mt][3], l0, l1);
                        mma_tf32(acc[mt][nt], al[mt][0], al[mt][1], al[mt][2], al[mt][3], b0, b1);
                    }
                    mma_tf32(acc[mt][nt], ah[mt][0], ah[mt][1], ah[mt][2], ah[mt][3], b0, b1);
                }
            }
        }
        __syncthreads();
    }

    if (FUSEM) {
        // per-row max & sum over this block's N columns, atomically merged
        unsigned* Mx = Mmax + (size_t)b * LL;
        float*    Ms = Msum + (size_t)b * LL;
        #pragma unroll
        for (int mt = 0; mt < 2; mt++) {
            float mx[2] = {-INFINITY, -INFINITY};
            float sm[2] = {0.f, 0.f};
            #pragma unroll
            for (int nt = 0; nt < 4; nt++) {
                int gc0 = n0 + wn + nt*8 + 2*lc;
                #pragma unroll
                for (int t = 0; t < 4; t++) {
                    int gn = gc0 + (t & 1);
                    int h = t >> 1;
                    if (gn < N) {
                        float v = acc[mt][nt][t];
                        mx[h] = fmaxf(mx[h], v);
                        sm[h] += v;
                    }
                }
            }
            #pragma unroll
            for (int o = 1; o <= 2; o <<= 1) {
                #pragma unroll
                for (int h = 0; h < 2; h++) {
                    mx[h] = fmaxf(mx[h], __shfl_xor_sync(0xFFFFFFFFu, mx[h], o));
                    sm[h] += __shfl_xor_sync(0xFFFFFFFFu, sm[h], o);
                }
            }
            if (lc == 0) {
                #pragma unroll
                for (int h = 0; h < 2; h++) {
                    int gm = m0 + wm + mt*16 + lr + h*8;
                    if (gm < M) {
                        atomicMax(&Mx[gm], fkey(mx[h]));
                        atomicAdd(&Ms[gm], sm[h]);
                    }
                }
            }
        }
    } else {
        #pragma unroll
        for (int mt = 0; mt < 2; mt++) {
            #pragma unroll
            for (int nt = 0; nt < 4; nt++) {
                int gr0 = m0 + wm + mt*16 + lr;
                int gc0 = n0 + wn + nt*8 + 2*lc;
                #pragma unroll
                for (int t = 0; t < 4; t++) {
                    int gm = gr0 + ((t >= 2) ? 8 : 0);
                    int gn = gc0 + (t & 1);
                    if (gm >= M || gn >= N) continue;
                    float v = acc[mt][nt][t] * alpha;
                    if (bias) v += bias[gn];
                    Cb[(size_t)gm * ldc_m + (size_t)gn * ldc_n] = v;
                }
            }
        }
    }
}

// -------- init fused M buffers --------
__global__ void minit_kernel() {
    int i = blockIdx.x * blockDim.x + threadIdx.x;
    if (i < BB * LL) { g_Mmax[i] = fkey(-INFINITY); g_Msum[i] = 0.f; }
}

// -------- gather sampled K rows --------
__global__ void gather_ksample_kernel(const int* __restrict__ idx, int U) {
    size_t t = (size_t)blockIdx.x * blockDim.x + threadIdx.x;
    size_t total = (size_t)BB * U * DD;
    if (t >= total) return;
    int d = (int)(t % DD);
    size_t rest = t / DD;
    int s = (int)(rest % U);
    int b = (int)(rest / U);
    g_ksamp[((size_t)b * U + s) * DD + d] = g_k[((size_t)b * LL + idx[s]) * DD + d];
}

// -------- per-batch bitonic top-k (desc by value, ties -> lower index) --------
__global__ void topk_kernel(int u) {
    __shared__ float sv[LL];
    __shared__ int   si[LL];
    int b = blockIdx.x;
    for (int i = threadIdx.x; i < LL; i += blockDim.x) {
        sv[i] = fdecode(g_Mmax[(size_t)b*LL + i]) - g_Msum[(size_t)b*LL + i] * (1.0f/(float)LL);
        si[i] = i;
    }
    __syncthreads();
    for (int k = 2; k <= LL; k <<= 1) {
        for (int j = k >> 1; j > 0; j >>= 1) {
            for (int t = threadIdx.x; t < LL; t += blockDim.x) {
                int ixj = t ^ j;
                if (ixj > t) {
                    bool dirDesc = ((t & k) == 0);
                    float va = sv[t], vb = sv[ixj];
                    int   ia = si[t], ib = si[ixj];
                    bool aBeforeB = (va > vb) || (va == vb && ia < ib);
                    bool swp = dirDesc ? !aBeforeB : aBeforeB;
                    if (swp) { sv[t] = vb; sv[ixj] = va; si[t] = ib; si[ixj] = ia; }
                }
            }
            __syncthreads();
        }
    }
    for (int i = threadIdx.x; i < u; i += blockDim.x) g_mtop[(size_t)b*u + i] = si[i];
}

// -------- gather Q_reduce rows --------
__global__ void gather_qr_kernel(int u) {
    size_t t = (size_t)blockIdx.x * blockDim.x + threadIdx.x;
    size_t total = (size_t)BB * u * DD;
    if (t >= total) return;
    int d = (int)(t % DD);
    size_t rest = t / DD;
    int uu = (int)(rest % u);
    int b  = (int)(rest / u);
    int l = g_mtop[(size_t)b*u + uu];
    g_qr[((size_t)b*u + uu) * DD + d] = g_q[((size_t)b*LL + l) * DD + d];
}

// -------- row softmax over L (in place on scores) --------
__global__ void softmax_kernel() {
    __shared__ float row[LL];
    __shared__ float red[256];
    size_t r = blockIdx.x;
    float* ptr = g_scores + r * (size_t)LL;
    float mx = -INFINITY;
    for (int i = threadIdx.x; i < LL; i += 256) { float x = ptr[i]; row[i] = x; mx = fmaxf(mx, x); }
    red[threadIdx.x] = mx; __syncthreads();
    for (int s = 128; s; s >>= 1) { if (threadIdx.x < s) red[threadIdx.x] = fmaxf(red[threadIdx.x], red[threadIdx.x+s]); __syncthreads(); }
    mx = red[0]; __syncthreads();
    float sm = 0.f;
    for (int i = threadIdx.x; i < LL; i += 256) { float e = __expf(row[i] - mx); row[i] = e; sm += e; }
    red[threadIdx.x] = sm; __syncthreads();
    for (int s = 128; s; s >>= 1) { if (threadIdx.x < s) red[threadIdx.x] += red[threadIdx.x+s]; __syncthreads(); }
    float inv = 1.f / red[0];
    for (int i = threadIdx.x; i < LL; i += 256) ptr[i] = row[i] * inv;
}

// -------- v mean over L --------
__global__ void vmean_zero_kernel() {
    int i = blockIdx.x * blockDim.x + threadIdx.x;
    if (i < BB * DD) g_vmean[i] = 0.f;
}
__global__ void vmean_kernel() {
    int b = blockIdx.x, ch = blockIdx.y;
    int d = threadIdx.x;
    float s = 0.f;
    int l0 = ch * 128;
    for (int l = l0; l < l0 + 128; l++) s += g_v[((size_t)b*LL + l) * DD + d];
    atomicAdd(&g_vmean[b*DD + d], s * (1.0f / (float)LL));
}

// -------- output: broadcast mean then scatter updated rows --------
__global__ void broadcast_out_kernel(float* __restrict__ out) {
    size_t t = (size_t)blockIdx.x * blockDim.x + threadIdx.x;
    if (t >= (size_t)BB*LL*DD) return;
    int d = (int)(t % DD);
    int b = (int)(t / ((size_t)LL*DD));
    out[t] = g_vmean[b*DD + d];
}
__global__ void scatter_out_kernel(float* __restrict__ out, int u) {
    size_t t = (size_t)blockIdx.x * blockDim.x + threadIdx.x;
    size_t total = (size_t)BB * u * DD;
    if (t >= total) return;
    int d = (int)(t % DD);
    size_t rest = t / DD;
    int uu = (int)(rest % u);
    int b  = (int)(rest / u);
    int l = g_mtop[(size_t)b*u + uu];
    out[((size_t)b*LL + l) * DD + d] = g_upd[((size_t)b*u + uu) * DD + d];
}

extern "C" void kernel_launch(void* const* d_in, const int* in_sizes, int n_in,
                              void* d_out, int out_size)
{
    const float* in1 = (const float*)d_in[0];
    const float* in2 = (const float*)d_in[1];
    const float* Wq  = (const float*)d_in[2];
    const float* bq  = (const float*)d_in[3];
    const float* Wk  = (const float*)d_in[4];
    const float* bk  = (const float*)d_in[5];
    const float* Wv  = (const float*)d_in[6];
    const float* bv  = (const float*)d_in[7];
    const int*   idx = (const int*)d_in[8];
    int U = in_sizes[8];
    int u = (U < LL) ? U : LL;
    float* out = (float*)d_out;

    float *q, *k, *v, *ksamp, *qr, *scores, *upd;
    unsigned* mmax; float* msum;
    cudaGetSymbolAddress((void**)&q,      g_q);
    cudaGetSymbolAddress((void**)&k,      g_k);
    cudaGetSymbolAddress((void**)&v,      g_v);
    cudaGetSymbolAddress((void**)&ksamp,  g_ksamp);
    cudaGetSymbolAddress((void**)&qr,     g_qr);
    cudaGetSymbolAddress((void**)&scores, g_scores);
    cudaGetSymbolAddress((void**)&upd,    g_upd);
    cudaGetSymbolAddress((void**)&mmax,   g_Mmax);
    cudaGetSymbolAddress((void**)&msum,   g_Msum);

    dim3 blk(256);
    const float scale = rsqrtf(512.0f);  // 1/sqrt(IN_CHANNELS)

    // 1) projections: y[o*L+s] = sum_c x[b,c,s]W[o,c]+b[o]
    //    (flat y IS the (L,D)-row-major q/k/v view after the reference reshape)
    //    q,k: 3xTF32 (selection-critical). v: 1xTF32 (smooth path).
    {
        dim3 grid(DD/64, LL/128, BB);
        gemm_tc_kernel<false,true,true,3,false><<<grid, blk>>>(in1, in2, Wq, q, LL, DD, CC, CIN,
            1L, (long)LL, (long)CC, 1L, 1L, (long)LL, (long)CIN*LL, 0L, (long)LL*DD, bq, 1.0f, nullptr, nullptr);
        gemm_tc_kernel<false,true,true,3,false><<<grid, blk>>>(in1, in2, Wk, k, LL, DD, CC, CIN,
            1L, (long)LL, (long)CC, 1L, 1L, (long)LL, (long)CIN*LL, 0L, (long)LL*DD, bk, 1.0f, nullptr, nullptr);
        gemm_tc_kernel<false,true,true,1,false><<<grid, blk>>>(in1, in2, Wv, v, LL, DD, CC, CIN,
            1L, (long)LL, (long)CC, 1L, 1L, (long)LL, (long)CIN*LL, 0L, (long)LL*DD, bv, 1.0f, nullptr, nullptr);
    }

    // 2) gather sampled K rows + init fused M buffers
    {
        size_t total = (size_t)BB * U * DD;
        gather_ksample_kernel<<<(unsigned)((total + 255) / 256), blk>>>(idx, U);
        minit_kernel<<<(BB*LL + 255)/256, blk>>>();
    }

    // 3) QKs fused with M-reduction: per-row max & sum of q[l,:].ksamp[s,:]
    //    (3xTF32; no QKs matrix materialized)
    {
        dim3 grid((U + 63)/64, LL/128, BB);
        gemm_tc_kernel<true,true,false,3,true><<<grid, blk>>>(q, nullptr, ksamp, nullptr, LL, U, DD, 0,
            (long)DD, 1L, (long)DD, 1L, 0L, 0L, (long)LL*DD, (long)U*DD, 0L, nullptr, 1.0f, mmax, msum);
    }

    // 4) top-k over M = max - sum/L
    topk_kernel<<<BB, 1024>>>(u);

    // 5) gather Q_reduce
    {
        size_t total = (size_t)BB * u * DD;
        gather_qr_kernel<<<(unsigned)((total + 255) / 256), blk>>>(u);
    }

    // 6) scores[u,l] = (Qr[u,:] . k[l,:]) * scale   (1xTF32, smooth path)
    {
        dim3 grid(LL/64, (u + 127)/128, BB);
        gemm_tc_kernel<true,true,false,1,false><<<grid, blk>>>(qr, nullptr, k, scores, u, LL, DD, 0,
            (long)DD, 1L, (long)DD, 1L, (long)LL, 1L, (long)u*DD, (long)LL*DD, (long)u*LL, nullptr, scale, nullptr, nullptr);
    }

    // 7) softmax over L (in place)
    softmax_kernel<<<BB*u, blk>>>();

    // 8) upd[u,d] = sum_l attn[u,l]*v[l,d]   (1xTF32, smooth path)
    {
        dim3 grid(DD/64, (u + 127)/128, BB);
        gemm_tc_kernel<true,false,false,1,false><<<grid, blk>>>(scores, nullptr, v, upd, u, DD, LL, 0,
            (long)LL, 1L, 1L, (long)DD, (long)DD, 1L, (long)u*LL, (long)LL*DD, (long)u*DD, nullptr, 1.0f, nullptr, nullptr);
    }

    // 9) v mean, broadcast, scatter
    vmean_zero_kernel<<<(BB*DD + 255)/256, blk>>>();
    {
        dim3 grid(BB, 32);
        vmean_kernel<<<grid, DD>>>();
    }
    {
        size_t total = (size_t)BB * LL * DD;
        broadcast_out_kernel<<<(unsigned)((total + 255)/256), blk>>>(out);
        size_t st = (size_t)BB * u * DD;
        scatter_out_kernel<<<(unsigned)((st + 255)/256), blk>>>(out, u);
    }
}